// round 1
// baseline (speedup 1.0000x reference)
#include <cuda_runtime.h>
#include <cuda_bf16.h>
#include <math_constants.h>

// Problem constants
#define BB 2
#define CC 1024
#define TT 2048
#define HH 16
#define GG 32
#define CHD 64          // C / H
#define CPG 32          // C / G
#define K3C 3072        // 3*C
#define EPSV 1e-5f

// ---------------- scratch (static device globals; no allocation) ----------------
__device__ float g_xn [(size_t)BB * CC * TT];        // 16.8 MB  groupnorm output
__device__ float g_qkv[(size_t)BB * K3C * TT];       // 50.3 MB  qkv projection
__device__ float g_a  [(size_t)BB * CC * TT];        // 16.8 MB  attention output

// ---------------- GroupNorm: one block per (b, g) ----------------
__global__ __launch_bounds__(256) void gn_kernel(
    const float* __restrict__ x,
    const float* __restrict__ scale,
    const float* __restrict__ bias,
    float* __restrict__ xn,
    float* __restrict__ out)
{
    int bg = blockIdx.x;
    int b = bg / GG;
    int g = bg % GG;
    const size_t base = ((size_t)b * CC + (size_t)g * CPG) * TT;
    const float* xp = x + base;
    const int n = CPG * TT;           // 65536
    int tid = threadIdx.x;

    float s = 0.f, ss = 0.f;
    for (int i = tid; i < n; i += 256) {
        float v = xp[i];
        s += v; ss += v * v;
    }
    __shared__ float rs[256], rss[256];
    rs[tid] = s; rss[tid] = ss;
    __syncthreads();
    for (int off = 128; off > 0; off >>= 1) {
        if (tid < off) { rs[tid] += rs[tid + off]; rss[tid] += rss[tid + off]; }
        __syncthreads();
    }
    float mean = rs[0] / (float)n;
    float var  = rss[0] / (float)n - mean * mean;
    float inv  = rsqrtf(var + EPSV);

    for (int i = tid; i < n; i += 256) {
        int c = g * CPG + i / TT;
        float v = (xp[i] - mean) * inv * scale[c] + bias[c];
        xn[base + i]  = v;
        out[base + i] = v;
    }
}

// ---------------- SGEMM: C[b] = A(MxK) * Bm[b](KxN) + bias (+ resid) ----------------
// K = 1024 (=C), N = 2048 (=T). 64x64 tile, BK=16, 256 threads, 4x4 per thread.
__global__ __launch_bounds__(256) void sgemm_kernel(
    const float* __restrict__ A,
    const float* __restrict__ Bm,     // batch stride K*N
    const float* __restrict__ bias,   // length M
    const float* __restrict__ resid,  // optional, batch M*N (may alias Cout)
    float* __restrict__ Cout,         // batch M*N
    int M, int has_resid)
{
    const int K = CC, N = TT;
    int b  = blockIdx.z;
    const float* Bp = Bm + (size_t)b * K * N;
    float*       Cp = Cout + (size_t)b * M * N;
    const float* Rp = resid + (size_t)b * M * N;

    int m0 = blockIdx.y * 64;
    int n0 = blockIdx.x * 64;
    int tid = threadIdx.x;
    int tx = tid & 15, ty = tid >> 4;

    __shared__ float As[16][68];   // transposed A tile [k][m], padded
    __shared__ float Bs[16][64];   // [k][n]

    int arow = tid >> 2, akq = tid & 3;    // A loader: row, k-quad
    int brow = tid >> 4, bnq = tid & 15;   // B loader: k-row, n-quad

    float acc[4][4];
#pragma unroll
    for (int i = 0; i < 4; i++)
#pragma unroll
        for (int j = 0; j < 4; j++) acc[i][j] = 0.f;

    for (int k0 = 0; k0 < K; k0 += 16) {
        float4 av = *(const float4*)(A  + (size_t)(m0 + arow) * K + k0 + akq * 4);
        float4 bv = *(const float4*)(Bp + (size_t)(k0 + brow) * N + n0 + bnq * 4);
        As[akq * 4 + 0][arow] = av.x;
        As[akq * 4 + 1][arow] = av.y;
        As[akq * 4 + 2][arow] = av.z;
        As[akq * 4 + 3][arow] = av.w;
        *(float4*)(&Bs[brow][bnq * 4]) = bv;
        __syncthreads();
#pragma unroll
        for (int kk = 0; kk < 16; kk++) {
            float4 ra = *(const float4*)(&As[kk][ty * 4]);
            float4 rb = *(const float4*)(&Bs[kk][tx * 4]);
            float aa[4] = { ra.x, ra.y, ra.z, ra.w };
            float bb[4] = { rb.x, rb.y, rb.z, rb.w };
#pragma unroll
            for (int i = 0; i < 4; i++)
#pragma unroll
                for (int j = 0; j < 4; j++)
                    acc[i][j] += aa[i] * bb[j];
        }
        __syncthreads();
    }

#pragma unroll
    for (int i = 0; i < 4; i++) {
        int m = m0 + ty * 4 + i;
        float bi = bias[m];
        float4 r = make_float4(acc[i][0] + bi, acc[i][1] + bi,
                               acc[i][2] + bi, acc[i][3] + bi);
        size_t off = (size_t)m * N + n0 + tx * 4;
        if (has_resid) {
            float4 rv = *(const float4*)(Rp + off);
            r.x += rv.x; r.y += rv.y; r.z += rv.z; r.w += rv.w;
        }
        *(float4*)(Cp + off) = r;
    }
}

// ---------------- Fused flash attention ----------------
// grid: (T/64, B*H). Per CTA: 64 query rows. Online softmax over causal s-tiles.
// smem tiles [c][s] padded to stride 68. 256 threads: r = tid>>2 (row), sub = tid&3.
__global__ __launch_bounds__(256) void attn_kernel(
    const float* __restrict__ qkv,
    const float* __restrict__ qk_bias,
    float* __restrict__ aout)
{
    const int LD = 68;
    extern __shared__ float sm[];
    float* Qs = sm;                 // [64][68]  q tile, [c][t]
    float* Ks = sm + 64 * LD;       // [64][68]  k tile, [c][s]
    float* Vs = sm + 2 * 64 * LD;   // [64][68]  v tile, [c][s]
    float* Ps = sm + 3 * 64 * LD;   // [64][68]  probs,  [r][s]

    int tt = blockIdx.x;
    int bh = blockIdx.y;
    int b = bh >> 4;      // H = 16
    int h = bh & 15;
    int t0 = tt * 64;

    const float* qbase = qkv + ((size_t)b * K3C + (size_t)h * 3 * CHD) * TT;
    const float* kbase = qbase + (size_t)CHD * TT;
    const float* vbase = qbase + (size_t)2 * CHD * TT;

    int tid = threadIdx.x;
    int r   = tid >> 2;
    int sub = tid & 3;
    int j0  = sub * 16;

    // load Q tile (once)
    for (int i = tid; i < 64 * 16; i += 256) {
        int c = i >> 4, s4 = (i & 15) * 4;
        *(float4*)(&Qs[c * LD + s4]) = *(const float4*)(qbase + (size_t)c * TT + t0 + s4);
    }

    float m_run = -CUDART_INF_F;
    float l_run = 0.f;
    float O[16];
#pragma unroll
    for (int i = 0; i < 16; i++) O[i] = 0.f;

    const float sc2 = 0.125f;   // 1/sqrt(CH) = 1/8

    int ntiles = tt + 1;        // causal
    for (int st = 0; st < ntiles; st++) {
        int s0 = st * 64;
        __syncthreads();
        // load K, V tiles
        for (int i = tid; i < 64 * 16; i += 256) {
            int c = i >> 4, s4 = (i & 15) * 4;
            *(float4*)(&Ks[c * LD + s4]) = *(const float4*)(kbase + (size_t)c * TT + s0 + s4);
            *(float4*)(&Vs[c * LD + s4]) = *(const float4*)(vbase + (size_t)c * TT + s0 + s4);
        }
        __syncthreads();

        // S[r, j0+jj] = sum_c Q[c][r] * K[c][j]
        float S[16];
#pragma unroll
        for (int jj = 0; jj < 16; jj++) S[jj] = 0.f;
#pragma unroll 4
        for (int c = 0; c < 64; c++) {
            float qc = Qs[c * LD + r];
            const float4* kp = (const float4*)(&Ks[c * LD + j0]);
#pragma unroll
            for (int g4 = 0; g4 < 4; g4++) {
                float4 kq = kp[g4];
                S[g4 * 4 + 0] += qc * kq.x;
                S[g4 * 4 + 1] += qc * kq.y;
                S[g4 * 4 + 2] += qc * kq.z;
                S[g4 * 4 + 3] += qc * kq.w;
            }
        }
        // scale + bias
        const float4* bp = (const float4*)(qk_bias + (size_t)(t0 + r) * TT + s0 + j0);
#pragma unroll
        for (int g4 = 0; g4 < 4; g4++) {
            float4 bq = bp[g4];
            S[g4 * 4 + 0] = S[g4 * 4 + 0] * sc2 + bq.x;
            S[g4 * 4 + 1] = S[g4 * 4 + 1] * sc2 + bq.y;
            S[g4 * 4 + 2] = S[g4 * 4 + 2] * sc2 + bq.z;
            S[g4 * 4 + 3] = S[g4 * 4 + 3] * sc2 + bq.w;
        }
        // causal mask (only diagonal tile can be partial)
        if (st == tt) {
#pragma unroll
            for (int jj = 0; jj < 16; jj++)
                if (j0 + jj > r) S[jj] = -CUDART_INF_F;
        }
        // row max across 16 local + 4 subs
        float mt = S[0];
#pragma unroll
        for (int jj = 1; jj < 16; jj++) mt = fmaxf(mt, S[jj]);
        mt = fmaxf(mt, __shfl_xor_sync(0xffffffffu, mt, 1));
        mt = fmaxf(mt, __shfl_xor_sync(0xffffffffu, mt, 2));
        float m_new = fmaxf(m_run, mt);
        float alpha = __expf(m_run - m_new);   // exp(-inf) = 0 on first tile

        float ps = 0.f;
#pragma unroll
        for (int jj = 0; jj < 16; jj++) {
            float p = __expf(S[jj] - m_new);
            S[jj] = p;
            ps += p;
        }
        ps += __shfl_xor_sync(0xffffffffu, ps, 1);
        ps += __shfl_xor_sync(0xffffffffu, ps, 2);
        l_run = l_run * alpha + ps;
        m_run = m_new;
#pragma unroll
        for (int i = 0; i < 16; i++) O[i] *= alpha;

        // publish P
        *(float4*)(&Ps[r * LD + j0 + 0])  = make_float4(S[0],  S[1],  S[2],  S[3]);
        *(float4*)(&Ps[r * LD + j0 + 4])  = make_float4(S[4],  S[5],  S[6],  S[7]);
        *(float4*)(&Ps[r * LD + j0 + 8])  = make_float4(S[8],  S[9],  S[10], S[11]);
        *(float4*)(&Ps[r * LD + j0 + 12]) = make_float4(S[12], S[13], S[14], S[15]);
        __syncthreads();

        // load full P row into registers
        float Prow[64];
#pragma unroll
        for (int m4 = 0; m4 < 16; m4++) {
            float4 pv = *(const float4*)(&Ps[r * LD + m4 * 4]);
            Prow[m4 * 4 + 0] = pv.x;
            Prow[m4 * 4 + 1] = pv.y;
            Prow[m4 * 4 + 2] = pv.z;
            Prow[m4 * 4 + 3] = pv.w;
        }
        // O[r, c] += sum_s P[r,s] * V[c][s]; thread owns c = 4*i + sub (bank-friendly)
#pragma unroll
        for (int i = 0; i < 16; i++) {
            int c = 4 * i + sub;
            const float4* vp = (const float4*)(&Vs[c * LD]);
            float acc = 0.f;
#pragma unroll
            for (int m4 = 0; m4 < 16; m4++) {
                float4 vv = vp[m4];
                acc += Prow[m4 * 4 + 0] * vv.x
                     + Prow[m4 * 4 + 1] * vv.y
                     + Prow[m4 * 4 + 2] * vv.z
                     + Prow[m4 * 4 + 3] * vv.w;
            }
            O[i] += acc;
        }
    }

    float invl = 1.f / l_run;
#pragma unroll
    for (int i = 0; i < 16; i++) {
        int c = 4 * i + sub;
        aout[((size_t)b * CC + (size_t)h * CHD + c) * TT + t0 + r] = O[i] * invl;
    }
}

// ---------------- launch ----------------
extern "C" void kernel_launch(void* const* d_in, const int* in_sizes, int n_in,
                              void* d_out, int out_size)
{
    const float* x        = (const float*)d_in[0];
    // d_in[1] = mask (bool tril) — causality is hardcoded
    const float* qk_bias  = (const float*)d_in[2];
    const float* gn_scale = (const float*)d_in[3];
    const float* gn_bias  = (const float*)d_in[4];
    const float* qkv_w    = (const float*)d_in[5];
    const float* qkv_b    = (const float*)d_in[6];
    const float* proj_w   = (const float*)d_in[7];
    const float* proj_b   = (const float*)d_in[8];
    float* out = (float*)d_out;

    float *xn_p, *qkv_p, *a_p;
    cudaGetSymbolAddress((void**)&xn_p,  g_xn);
    cudaGetSymbolAddress((void**)&qkv_p, g_qkv);
    cudaGetSymbolAddress((void**)&a_p,   g_a);

    // 1. GroupNorm -> g_xn and residual baseline into out
    gn_kernel<<<BB * GG, 256>>>(x, gn_scale, gn_bias, xn_p, out);

    // 2. QKV GEMM: (3072 x 1024) @ (1024 x 2048) per batch
    {
        dim3 grid(TT / 64, K3C / 64, BB);
        sgemm_kernel<<<grid, 256>>>(qkv_w, xn_p, qkv_b, qkv_p /*unused*/, qkv_p, K3C, 0);
    }

    // 3. Fused causal attention with bias
    {
        int smem = 4 * 64 * 68 * (int)sizeof(float);   // 69632
        cudaFuncSetAttribute(attn_kernel, cudaFuncAttributeMaxDynamicSharedMemorySize, smem);
        dim3 grid(TT / 64, BB * HH);
        attn_kernel<<<grid, 256, smem>>>(qkv_p, qk_bias, a_p);
    }

    // 4. Projection + bias + residual (out already holds xn)
    {
        dim3 grid(TT / 64, CC / 64, BB);
        sgemm_kernel<<<grid, 256>>>(proj_w, a_p, proj_b, out, out, CC, 1);
    }
}

// round 4
// speedup vs baseline: 3.3309x; 3.3309x over previous
#include <cuda_runtime.h>
#include <math_constants.h>

#define BB 2
#define CC 1024
#define TT 2048
#define HH 16
#define GG 32
#define CHD 64
#define CPG 32
#define K3C 3072
#define EPSV 1e-5f

// ---------------- scratch ----------------
__device__ float g_xn [(size_t)BB * CC * TT];
__device__ float g_qkv[(size_t)BB * K3C * TT];
__device__ float g_a  [(size_t)BB * CC * TT];

// ---------------- helpers ----------------
__device__ __forceinline__ unsigned f2tf(float f) {
    unsigned u; asm("cvt.rna.tf32.f32 %0, %1;" : "=r"(u) : "f"(f)); return u;
}
__device__ __forceinline__ void mma8(float& d0, float& d1, float& d2, float& d3,
                                     unsigned a0, unsigned a1, unsigned a2, unsigned a3,
                                     unsigned b0, unsigned b1)
{
    asm volatile("mma.sync.aligned.m16n8k8.row.col.f32.tf32.tf32.f32 "
                 "{%0,%1,%2,%3}, {%4,%5,%6,%7}, {%8,%9}, {%0,%1,%2,%3};\n"
                 : "+f"(d0), "+f"(d1), "+f"(d2), "+f"(d3)
                 : "r"(a0), "r"(a1), "r"(a2), "r"(a3), "r"(b0), "r"(b1));
}

// ---------------- GroupNorm ----------------
__global__ __launch_bounds__(256) void gn_kernel(
    const float* __restrict__ x, const float* __restrict__ scale,
    const float* __restrict__ bias, float* __restrict__ xn, float* __restrict__ out)
{
    int bg = blockIdx.x;
    int b = bg / GG, g = bg % GG;
    const size_t base = ((size_t)b * CC + (size_t)g * CPG) * TT;
    const float* xp = x + base;
    const int n = CPG * TT;
    int tid = threadIdx.x;

    float s = 0.f, ss = 0.f;
    for (int i = tid; i < n; i += 256) { float v = xp[i]; s += v; ss += v * v; }
    __shared__ float rs[256], rss[256];
    rs[tid] = s; rss[tid] = ss;
    __syncthreads();
    for (int off = 128; off > 0; off >>= 1) {
        if (tid < off) { rs[tid] += rs[tid + off]; rss[tid] += rss[tid + off]; }
        __syncthreads();
    }
    float mean = rs[0] / (float)n;
    float var  = rss[0] / (float)n - mean * mean;
    float inv  = rsqrtf(var + EPSV);
    for (int i = tid; i < n; i += 256) {
        int c = g * CPG + i / TT;
        float v = (xp[i] - mean) * inv * scale[c] + bias[c];
        xn[base + i] = v;
        out[base + i] = v;
    }
}

// ---------------- TF32 tensor-core GEMM ----------------
// C[b] = A(MxK) @ Bm[b](KxN) + bias (+resid).  K=1024, N=2048.
// CTA 128x128, BK=16, 256 thr (8 warps, 2x4), warp tile 64x32 via m16n8k8.
// smem holds tiles pre-permuted into mma fragment layout.
__global__ __launch_bounds__(256) void gemm_tf32(
    const float* __restrict__ A, const float* __restrict__ Bm,
    const float* __restrict__ bias, const float* __restrict__ resid,
    float* __restrict__ Cout, int M, int has_resid)
{
    const int K = CC, N = TT;
    int b = blockIdx.z;
    const float* Bp = Bm + (size_t)b * K * N;
    float*       Cp = Cout + (size_t)b * M * N;
    const float* Rp = resid + (size_t)b * M * N;
    int m0 = blockIdx.y * 128, n0 = blockIdx.x * 128;
    int tid = threadIdx.x, lane = tid & 31, wid = tid >> 5;
    int wm = wid >> 2, wn = wid & 3;

    __shared__ float As[2][2048];   // frag-layout tiles, 8KB per buffer
    __shared__ float Bs[2][2048];

    int la_m = tid >> 2;            // 0..63
    int la_k = (tid & 3) * 4;       // 0,4,8,12
    int lb_k = tid >> 5;            // 0..7
    int lb_n = (tid & 31) * 4;      // 0..124

    float4 stA[2], stB[2];
    float acc[4][4][4];
#pragma unroll
    for (int f = 0; f < 4; f++)
#pragma unroll
        for (int g = 0; g < 4; g++)
#pragma unroll
            for (int q = 0; q < 4; q++) acc[f][g][q] = 0.f;

    // prologue load of tile 0
#pragma unroll
    for (int p = 0; p < 2; p++) {
        stA[p] = *(const float4*)(A  + (size_t)(m0 + p * 64 + la_m) * K + la_k);
        stB[p] = *(const float4*)(Bp + (size_t)(p * 8 + lb_k) * N + n0 + lb_n);
    }
    // scatter into buf 0
    {
        float* as = As[0]; float* bs = Bs[0];
#pragma unroll
        for (int p = 0; p < 2; p++) {
            int m = p * 64 + la_m, mi = m >> 4, r = m & 15;
            float va[4] = { stA[p].x, stA[p].y, stA[p].z, stA[p].w };
#pragma unroll
            for (int j = 0; j < 4; j++) {
                int k = la_k + j, ki = k >> 3, c = k & 7;
                as[(((ki * 8 + mi) * 32) + (r & 7) * 4 + (c & 3)) * 4 + (((c >> 2) << 1) | (r >> 3))]
                    = __uint_as_float(f2tf(va[j]));
            }
            int k = p * 8 + lb_k, ki = k >> 3, kc = k & 7;
            float vb[4] = { stB[p].x, stB[p].y, stB[p].z, stB[p].w };
#pragma unroll
            for (int j = 0; j < 4; j++) {
                int nn = lb_n + j, ni = nn >> 3;
                bs[(((ki * 16 + ni) * 32) + (nn & 7) * 4 + (kc & 3)) * 2 + (kc >> 2)]
                    = __uint_as_float(f2tf(vb[j]));
            }
        }
    }
    __syncthreads();

    const int NTILE = K / 16;
    for (int kt = 0; kt < NTILE; kt++) {
        int cur = kt & 1;
        if (kt + 1 < NTILE) {
            int k0 = (kt + 1) * 16;
#pragma unroll
            for (int p = 0; p < 2; p++) {
                stA[p] = *(const float4*)(A  + (size_t)(m0 + p * 64 + la_m) * K + k0 + la_k);
                stB[p] = *(const float4*)(Bp + (size_t)(k0 + p * 8 + lb_k) * N + n0 + lb_n);
            }
        }
        // compute on cur
        const float4* As4 = (const float4*)As[cur];
        const float2* Bs2 = (const float2*)Bs[cur];
#pragma unroll
        for (int ki = 0; ki < 2; ki++) {
            float4 af[4]; float2 bf[4];
#pragma unroll
            for (int f = 0; f < 4; f++) af[f] = As4[(ki * 8 + wm * 4 + f) * 32 + lane];
#pragma unroll
            for (int g = 0; g < 4; g++) bf[g] = Bs2[(ki * 16 + wn * 4 + g) * 32 + lane];
#pragma unroll
            for (int f = 0; f < 4; f++)
#pragma unroll
                for (int g = 0; g < 4; g++)
                    mma8(acc[f][g][0], acc[f][g][1], acc[f][g][2], acc[f][g][3],
                         __float_as_uint(af[f].x), __float_as_uint(af[f].y),
                         __float_as_uint(af[f].z), __float_as_uint(af[f].w),
                         __float_as_uint(bf[g].x), __float_as_uint(bf[g].y));
        }
        if (kt + 1 < NTILE) {
            float* as = As[cur ^ 1]; float* bs = Bs[cur ^ 1];
#pragma unroll
            for (int p = 0; p < 2; p++) {
                int m = p * 64 + la_m, mi = m >> 4, r = m & 15;
                float va[4] = { stA[p].x, stA[p].y, stA[p].z, stA[p].w };
#pragma unroll
                for (int j = 0; j < 4; j++) {
                    int k = la_k + j, ki = k >> 3, c = k & 7;
                    as[(((ki * 8 + mi) * 32) + (r & 7) * 4 + (c & 3)) * 4 + (((c >> 2) << 1) | (r >> 3))]
                        = __uint_as_float(f2tf(va[j]));
                }
                int k = p * 8 + lb_k, ki = k >> 3, kc = k & 7;
                float vb[4] = { stB[p].x, stB[p].y, stB[p].z, stB[p].w };
#pragma unroll
                for (int j = 0; j < 4; j++) {
                    int nn = lb_n + j, ni = nn >> 3;
                    bs[(((ki * 16 + ni) * 32) + (nn & 7) * 4 + (kc & 3)) * 2 + (kc >> 2)]
                        = __uint_as_float(f2tf(vb[j]));
                }
            }
        }
        __syncthreads();
    }

    // epilogue
#pragma unroll
    for (int f = 0; f < 4; f++) {
        int mrow = m0 + wm * 64 + f * 16 + (lane >> 2);
#pragma unroll
        for (int half = 0; half < 2; half++) {
            int m = mrow + half * 8;
            float bi = bias[m];
#pragma unroll
            for (int g = 0; g < 4; g++) {
                int nn = n0 + wn * 32 + g * 8 + (lane & 3) * 2;
                float2 v;
                v.x = acc[f][g][half * 2 + 0] + bi;
                v.y = acc[f][g][half * 2 + 1] + bi;
                size_t off = (size_t)m * N + nn;
                if (has_resid) {
                    float2 rv = *(const float2*)(Rp + off);
                    v.x += rv.x; v.y += rv.y;
                }
                *(float2*)(Cp + off) = v;
            }
        }
    }
}

// ---------------- TF32 flash attention ----------------
// Per CTA: 64 q rows, loop over causal 64-wide s tiles. 8 warps: wm=wid>>1 (m16 row
// block), wn=wid&1 (32-col half). All matmuls via m16n8k8 tf32 with fragment-layout smem.
__global__ __launch_bounds__(256) void attn_tf32(
    const float* __restrict__ qkv, const float* __restrict__ qk_bias,
    float* __restrict__ aout)
{
    extern __shared__ float sm[];
    float* Qf   = sm;             // 4096 floats, A-frag layout
    float* Kf   = sm + 4096;      // B-frag layout (k=c blocks, n=s blocks)
    float* Vf   = sm + 8192;      // B-frag layout (k=s blocks, n=c blocks)
    float* Pf   = sm + 12288;     // A-frag layout (m=t blocks, k=s blocks)
    float* smax = sm + 16384;     // [2][64]
    float* ssum = sm + 16512;     // [2][64]

    int tt = (int)gridDim.x - 1 - (int)blockIdx.x;   // heavy tiles first
    int bh = blockIdx.y;
    int b = bh >> 4, h = bh & 15;
    int t0 = tt * 64;

    const float* qb = qkv + ((size_t)b * K3C + (size_t)h * 3 * CHD) * TT;
    const float* kb = qb + (size_t)CHD * TT;
    const float* vb = qb + (size_t)2 * CHD * TT;

    int tid = threadIdx.x, lane = tid & 31, wid = tid >> 5;
    int wm = wid >> 1, wn = wid & 1;
    int gq = lane >> 2, qd = lane & 3;

    // load Q tile (t,c), scatter to A-frag layout as tf32
#pragma unroll
    for (int it = 0; it < 4; it++) {
        int li = tid + it * 256;
        int c = li >> 4;
        int tq = (li & 15) * 4;
        float4 v = *(const float4*)(qb + (size_t)c * TT + t0 + tq);
        int ki = c >> 3, cc = c & 7;
        float va[4] = { v.x, v.y, v.z, v.w };
#pragma unroll
        for (int j = 0; j < 4; j++) {
            int t = tq + j, mi = t >> 4, r = t & 15;
            Qf[(((ki * 4 + mi) * 32) + (r & 7) * 4 + (cc & 3)) * 4 + (((cc >> 2) << 1) | (r >> 3))]
                = __uint_as_float(f2tf(va[j]));
        }
    }

    float mrunA = -CUDART_INF_F, mrunB = -CUDART_INF_F;
    float lrunA = 0.f, lrunB = 0.f;
    float O[4][4];
#pragma unroll
    for (int g = 0; g < 4; g++)
#pragma unroll
        for (int q = 0; q < 4; q++) O[g][q] = 0.f;

    const float sc = 0.125f;
    int rA = wm * 16 + gq;
    int rB = rA + 8;
    int tArow = t0 + rA, tBrow = t0 + rB;

    for (int st = 0; st <= tt; st++) {
        int s0 = st * 64;
        __syncthreads();   // prev iter done with Kf/Vf/Pf
        // load K, V tiles, scatter to B-frag layouts as tf32
#pragma unroll
        for (int it = 0; it < 4; it++) {
            int li = tid + it * 256;
            int c = li >> 4;
            int sq = (li & 15) * 4;
            float4 kv = *(const float4*)(kb + (size_t)c * TT + s0 + sq);
            float4 vv = *(const float4*)(vb + (size_t)c * TT + s0 + sq);
            float ka[4] = { kv.x, kv.y, kv.z, kv.w };
            float va[4] = { vv.x, vv.y, vv.z, vv.w };
#pragma unroll
            for (int j = 0; j < 4; j++) {
                int s = sq + j;
                Kf[((((c >> 3) * 8 + (s >> 3)) * 32) + (s & 7) * 4 + (c & 3)) * 2 + ((c & 7) >> 2)]
                    = __uint_as_float(f2tf(ka[j]));
                Vf[((((s >> 3) * 8 + (c >> 3)) * 32) + (c & 7) * 4 + (s & 3)) * 2 + ((s & 7) >> 2)]
                    = __uint_as_float(f2tf(va[j]));
            }
        }
        __syncthreads();

        // S = Q^T K
        float S[4][4];
#pragma unroll
        for (int g = 0; g < 4; g++)
#pragma unroll
            for (int q = 0; q < 4; q++) S[g][q] = 0.f;
        const float4* Q4 = (const float4*)Qf;
        const float2* K2 = (const float2*)Kf;
#pragma unroll
        for (int ki = 0; ki < 8; ki++) {
            float4 a = Q4[(ki * 4 + wm) * 32 + lane];
            unsigned a0 = __float_as_uint(a.x), a1 = __float_as_uint(a.y);
            unsigned a2 = __float_as_uint(a.z), a3 = __float_as_uint(a.w);
#pragma unroll
            for (int g = 0; g < 4; g++) {
                float2 bb = K2[(ki * 8 + wn * 4 + g) * 32 + lane];
                mma8(S[g][0], S[g][1], S[g][2], S[g][3], a0, a1, a2, a3,
                     __float_as_uint(bb.x), __float_as_uint(bb.y));
            }
        }
        // scale + bias + causal mask
#pragma unroll
        for (int g = 0; g < 4; g++) {
            int sCol = s0 + wn * 32 + g * 8 + qd * 2;
            float2 bA = *(const float2*)(qk_bias + (size_t)tArow * TT + sCol);
            float2 bB = *(const float2*)(qk_bias + (size_t)tBrow * TT + sCol);
            S[g][0] = S[g][0] * sc + bA.x;
            S[g][1] = S[g][1] * sc + bA.y;
            S[g][2] = S[g][2] * sc + bB.x;
            S[g][3] = S[g][3] * sc + bB.y;
            if (st == tt) {
                if (sCol     > tArow) S[g][0] = -CUDART_INF_F;
                if (sCol + 1 > tArow) S[g][1] = -CUDART_INF_F;
                if (sCol     > tBrow) S[g][2] = -CUDART_INF_F;
                if (sCol + 1 > tBrow) S[g][3] = -CUDART_INF_F;
            }
        }
        // row max within warp
        float mA = fmaxf(fmaxf(S[0][0], S[0][1]), fmaxf(S[1][0], S[1][1]));
        mA = fmaxf(mA, fmaxf(fmaxf(S[2][0], S[2][1]), fmaxf(S[3][0], S[3][1])));
        float mB = fmaxf(fmaxf(S[0][2], S[0][3]), fmaxf(S[1][2], S[1][3]));
        mB = fmaxf(mB, fmaxf(fmaxf(S[2][2], S[2][3]), fmaxf(S[3][2], S[3][3])));
        mA = fmaxf(mA, __shfl_xor_sync(0xffffffffu, mA, 1));
        mA = fmaxf(mA, __shfl_xor_sync(0xffffffffu, mA, 2));
        mB = fmaxf(mB, __shfl_xor_sync(0xffffffffu, mB, 1));
        mB = fmaxf(mB, __shfl_xor_sync(0xffffffffu, mB, 2));
        if (qd == 0) { smax[wn * 64 + rA] = mA; smax[wn * 64 + rB] = mB; }
        __syncthreads();
        float mnewA = fmaxf(mrunA, fmaxf(smax[rA], smax[64 + rA]));
        float mnewB = fmaxf(mrunB, fmaxf(smax[rB], smax[64 + rB]));
        float alA = __expf(mrunA - mnewA);
        float alB = __expf(mrunB - mnewB);
        mrunA = mnewA; mrunB = mnewB;

        float sumA = 0.f, sumB = 0.f;
#pragma unroll
        for (int g = 0; g < 4; g++) {
            S[g][0] = __expf(S[g][0] - mnewA); sumA += S[g][0];
            S[g][1] = __expf(S[g][1] - mnewA); sumA += S[g][1];
            S[g][2] = __expf(S[g][2] - mnewB); sumB += S[g][2];
            S[g][3] = __expf(S[g][3] - mnewB); sumB += S[g][3];
        }
        sumA += __shfl_xor_sync(0xffffffffu, sumA, 1);
        sumA += __shfl_xor_sync(0xffffffffu, sumA, 2);
        sumB += __shfl_xor_sync(0xffffffffu, sumB, 1);
        sumB += __shfl_xor_sync(0xffffffffu, sumB, 2);
        if (qd == 0) { ssum[wn * 64 + rA] = sumA; ssum[wn * 64 + rB] = sumB; }

        // scatter P into A-frag layout (tf32)
#pragma unroll
        for (int g = 0; g < 4; g++) {
            int kiP = wn * 4 + g;
#pragma unroll
            for (int j = 0; j < 2; j++) {
                int cc = qd * 2 + j;
                int base4 = ((kiP * 4 + wm) * 32 + gq * 4 + (cc & 3)) * 4;
                int hi = (cc >> 2) << 1;
                Pf[base4 + hi + 0] = __uint_as_float(f2tf(S[g][0 + j]));
                Pf[base4 + hi + 1] = __uint_as_float(f2tf(S[g][2 + j]));
            }
        }
        __syncthreads();
        float tsA = ssum[rA] + ssum[64 + rA];
        float tsB = ssum[rB] + ssum[64 + rB];
        lrunA = lrunA * alA + tsA;
        lrunB = lrunB * alB + tsB;
#pragma unroll
        for (int g = 0; g < 4; g++) {
            O[g][0] *= alA; O[g][1] *= alA; O[g][2] *= alB; O[g][3] *= alB;
        }
        // O += P V^T  (m=t, n=c, k=s)
        const float4* P4 = (const float4*)Pf;
        const float2* V2 = (const float2*)Vf;
#pragma unroll
        for (int ki = 0; ki < 8; ki++) {
            float4 a = P4[(ki * 4 + wm) * 32 + lane];
            unsigned a0 = __float_as_uint(a.x), a1 = __float_as_uint(a.y);
            unsigned a2 = __float_as_uint(a.z), a3 = __float_as_uint(a.w);
#pragma unroll
            for (int g = 0; g < 4; g++) {
                float2 bb = V2[(ki * 8 + wn * 4 + g) * 32 + lane];
                mma8(O[g][0], O[g][1], O[g][2], O[g][3], a0, a1, a2, a3,
                     __float_as_uint(bb.x), __float_as_uint(bb.y));
            }
        }
    }

    // write A output: a[(b*C + h*64 + c)*T + t]
    float invA = 1.f / lrunA, invB = 1.f / lrunB;
    size_t obase = ((size_t)b * CC + (size_t)h * CHD) * TT;
#pragma unroll
    for (int g = 0; g < 4; g++) {
        int c0 = wn * 32 + g * 8 + qd * 2;
        aout[obase + (size_t)(c0    ) * TT + tArow] = O[g][0] * invA;
        aout[obase + (size_t)(c0 + 1) * TT + tArow] = O[g][1] * invA;
        aout[obase + (size_t)(c0    ) * TT + tBrow] = O[g][2] * invB;
        aout[obase + (size_t)(c0 + 1) * TT + tBrow] = O[g][3] * invB;
    }
}

// ---------------- launch ----------------
extern "C" void kernel_launch(void* const* d_in, const int* in_sizes, int n_in,
                              void* d_out, int out_size)
{
    const float* x        = (const float*)d_in[0];
    const float* qk_bias  = (const float*)d_in[2];
    const float* gn_scale = (const float*)d_in[3];
    const float* gn_bias  = (const float*)d_in[4];
    const float* qkv_w    = (const float*)d_in[5];
    const float* qkv_b    = (const float*)d_in[6];
    const float* proj_w   = (const float*)d_in[7];
    const float* proj_b   = (const float*)d_in[8];
    float* out = (float*)d_out;

    float *xn_p, *qkv_p, *a_p;
    cudaGetSymbolAddress((void**)&xn_p,  g_xn);
    cudaGetSymbolAddress((void**)&qkv_p, g_qkv);
    cudaGetSymbolAddress((void**)&a_p,   g_a);

    gn_kernel<<<BB * GG, 256>>>(x, gn_scale, gn_bias, xn_p, out);

    {   // QKV: (3072x1024) @ (1024x2048)
        dim3 grid(TT / 128, K3C / 128, BB);
        gemm_tf32<<<grid, 256>>>(qkv_w, xn_p, qkv_b, qkv_p, qkv_p, K3C, 0);
    }
    {   // attention
        int smem = 16640 * (int)sizeof(float);   // 66560 B
        cudaFuncSetAttribute(attn_tf32, cudaFuncAttributeMaxDynamicSharedMemorySize, smem);
        dim3 grid(TT / 64, BB * HH);
        attn_tf32<<<grid, 256, smem>>>(qkv_p, qk_bias, a_p);
    }
    {   // proj + residual
        dim3 grid(TT / 128, CC / 128, BB);
        gemm_tf32<<<grid, 256>>>(proj_w, a_p, proj_b, out, out, CC, 1);
    }
}